// round 14
// baseline (speedup 1.0000x reference)
#include <cuda_runtime.h>
#include <math.h>

#define BB   16
#define SS   32
#define NTT  2029
#define NN   256
#define PIX  (NN*NN)
#define IMG  (BB*PIX)

__device__ float g_rec [BB*PIX];
__device__ float g_h0  [BB*64 *128*128];
__device__ float g_h1  [BB*128*64 *64 ];
__device__ float g_h2  [BB*256*32 *32 ];
__device__ float g_h3  [BB*512*16 *16 ];
__device__ float g_h4  [BB*512*8  *8  ];
__device__ float g_u4  [BB*512*16 *16 ];
__device__ float g_u3  [BB*256*32 *32 ];
__device__ float g_u2  [BB*128*64 *64 ];
__device__ float g_u1  [BB*64 *128*128];
__device__ float g_wpack[4*512*512*4];
__device__ float g_mm[2];
__device__ float g_scale[512];
__device__ float g_shift[512];

// ---------------- backprojection (bit-exact passing form — DO NOT TOUCH) -----
__global__ void k_backproject(const float* __restrict__ sig,
                              const float* __restrict__ trans)
{
    int idx = blockIdx.x * blockDim.x + threadIdx.x;
    if (idx >= PIX) return;
    int j = idx & 255, i = idx >> 8;
    const float startf = -0.0125f, stopf = 0.0125f;
    float stepj = __fdiv_rn((float)j, 255.0f);
    float stepi = __fdiv_rn((float)i, 255.0f);
    float cj = __fadd_rn(__fmul_rn(startf, __fsub_rn(1.0f, stepj)), __fmul_rn(stopf, stepj));
    float ci = __fadd_rn(__fmul_rn(startf, __fsub_rn(1.0f, stepi)), __fmul_rn(stopf, stepi));
    float acc[BB];
#pragma unroll
    for (int b = 0; b < BB; b++) acc[b] = 0.f;
    for (int s = 0; s < SS; s++) {
        float dx = __fsub_rn(cj, __ldg(&trans[2*s+0]));
        float dy = __fsub_rn(ci, __ldg(&trans[2*s+1]));
        float dd = __fadd_rn(__fmul_rn(dx, dx), __fmul_rn(dy, dy));
        float d  = __fsqrt_rn(dd);
        float v  = __fadd_rn(__fsub_rn(__fdiv_rn(__fmul_rn(d, 40000000.0f), 1572.0f), 113.0f), 1.0f);
        int t = (int)rintf(v);
        t = max(0, min(t, NTT-1));
        const float* sp = sig + (size_t)t * SS + s;
#pragma unroll
        for (int b = 0; b < BB; b++) acc[b] += __ldg(sp + (size_t)b * NTT * SS);
    }
#pragma unroll
    for (int b = 0; b < BB; b++) g_rec[(size_t)b * PIX + idx] = acc[b] * (1.0f / 32.0f);
}

__device__ void atomicMinF(float* a, float v) {
    int old = __float_as_int(*a);
    while (v < __int_as_float(old)) {
        int prev = atomicCAS((int*)a, old, __float_as_int(v));
        if (prev == old) break; old = prev;
    }
}
__device__ void atomicMaxF(float* a, float v) {
    int old = __float_as_int(*a);
    while (v > __int_as_float(old)) {
        int prev = atomicCAS((int*)a, old, __float_as_int(v));
        if (prev == old) break; old = prev;
    }
}
__global__ void k_minmax_init() { g_mm[0] = INFINITY; g_mm[1] = -INFINITY; }

__global__ void k_minmax_reduce()
{
    float mn = INFINITY, mx = -INFINITY;
    for (int i = blockIdx.x * blockDim.x + threadIdx.x; i < IMG; i += gridDim.x * blockDim.x) {
        float v = g_rec[i]; mn = fminf(mn, v); mx = fmaxf(mx, v);
    }
    __shared__ float smn[256], smx[256];
    int t = threadIdx.x;
    smn[t] = mn; smx[t] = mx;
    __syncthreads();
    for (int o = 128; o > 0; o >>= 1) {
        if (t < o) { smn[t] = fminf(smn[t], smn[t+o]); smx[t] = fmaxf(smx[t], smx[t+o]); }
        __syncthreads();
    }
    if (t == 0) { atomicMinF(&g_mm[0], smn[0]); atomicMaxF(&g_mm[1], smx[0]); }
}

__global__ void k_normalize(float* __restrict__ out_rec, int copy_out)
{
    int i = blockIdx.x * blockDim.x + threadIdx.x;
    if (i >= IMG) return;
    float mn = g_mm[0], mx = g_mm[1];
    float v = __fdiv_rn(__fsub_rn(g_rec[i], mn), __fsub_rn(mx, mn));
    g_rec[i] = v;
    if (copy_out) out_rec[i] = v;
}

// ---------------- conv d0 (Cin=1): direct, taps ascending (proven) ----------
__global__ void __launch_bounds__(256) k_conv_d0(const float* __restrict__ w)
{
    __shared__ float ws[1024];
    for (int i = threadIdx.x; i < 1024; i += 256) ws[i] = w[i];
    __syncthreads();
    int idx = blockIdx.x * 256 + threadIdx.x;        // 16*128*128
    int x = idx & 127, y = (idx >> 7) & 127, b = idx >> 14;
    float patch[16];
#pragma unroll
    for (int t = 0; t < 16; t++) {
        int iy = 2*y - 1 + (t >> 2), ix = 2*x - 1 + (t & 3);
        patch[t] = (iy >= 0 && iy < 256 && ix >= 0 && ix < 256)
                   ? g_rec[b * PIX + iy * 256 + ix] : 0.f;
    }
    float* op = g_h0 + ((size_t)b * 64 << 14) + (y << 7) + x;
    for (int co = 0; co < 64; co++) {
        float a = 0.f;
#pragma unroll
        for (int t = 0; t < 16; t++) a += patch[t] * ws[co * 16 + t];
        op[(size_t)co << 14] = a;
    }
}

// =====================================================================
// conv stride-2 k4 p1 — v1.5 FFMA (R7 body) + NT template {64,32,16}
// =====================================================================
template<int Cin, int Hi, int Wi, int Cout, int ACT, int NT>
__device__ __forceinline__ void conv_v15(const float* __restrict__ in,
                                         const float* __restrict__ w,
                                         float* __restrict__ out)
{
    constexpr int Ho = Hi >> 1, Wo = Wi >> 1;
    constexpr int HoWo = Ho * Wo;
    constexpr int HiWi = Hi * Wi;
    constexpr int NQ = NT / 16;
    const int m0 = blockIdx.y * 64;
    const int p0 = blockIdx.x * NT;

    __shared__ __align__(16) float As[2][16][68];
    __shared__ __align__(16) float Bs[2][16][NT + 4];

    const int tid  = threadIdx.x;
    const int kk   = tid & 15;
    const int rowq = tid >> 4;
    const int ky = kk >> 2, kx = kk & 3;
    const int tx = kk, ty = rowq;

    int woff[4];
#pragma unroll
    for (int q = 0; q < 4; q++)
        woff[q] = (m0 + rowq + 16 * q) * Cin * 16 + kk;

    int bofs[NQ];
#pragma unroll
    for (int q = 0; q < NQ; q++) {
        int p = p0 + rowq + 16 * q;
        int b = p / HoWo; int r = p - b * HoWo;
        int y = r / Wo;   int x = r - y * Wo;
        int iy = 2*y - 1 + ky, ix = 2*x - 1 + kx;
        bool v = iy >= 0 && iy < Hi && ix >= 0 && ix < Wi;
        bofs[q] = v ? (b * Cin * HiWi + iy * Wi + ix) : -1;
    }

    float aR[4], bR[NQ];
#pragma unroll
    for (int q = 0; q < 4; q++) aR[q] = __ldg(w + woff[q]);
#pragma unroll
    for (int q = 0; q < NQ; q++) {
        float v = 0.f;
        if (bofs[q] >= 0) {
            v = __ldg(in + bofs[q]);
            if (ACT) v = (v >= 0.f) ? v : 0.2f * v;
        }
        bR[q] = v;
    }
#pragma unroll
    for (int q = 0; q < 4;  q++) As[0][kk][rowq + 16*q] = aR[q];
#pragma unroll
    for (int q = 0; q < NQ; q++) Bs[0][kk][rowq + 16*q] = bR[q];
    __syncthreads();

    float acc[4][NQ];
#pragma unroll
    for (int i = 0; i < 4; i++)
#pragma unroll
        for (int j = 0; j < NQ; j++) acc[i][j] = 0.f;

    int buf = 0;
    for (int cci = 0; cci < Cin; cci++) {
        const bool more = (cci + 1 < Cin);
        if (more) {
            const float* wp = w + (size_t)(cci + 1) * 16;
            const float* ip = in + (size_t)(cci + 1) * HiWi;
#pragma unroll
            for (int q = 0; q < 4; q++) aR[q] = __ldg(wp + woff[q]);
#pragma unroll
            for (int q = 0; q < NQ; q++) {
                float v = 0.f;
                if (bofs[q] >= 0) {
                    v = __ldg(ip + bofs[q]);
                    if (ACT) v = (v >= 0.f) ? v : 0.2f * v;
                }
                bR[q] = v;
            }
        }
#pragma unroll
        for (int k = 0; k < 16; k++) {
            float4 a4 = *(const float4*)(&As[buf][k][ty * 4]);
            float av[4] = {a4.x, a4.y, a4.z, a4.w};
            float bv[NQ];
            if constexpr (NQ == 4) {
                float4 b4 = *(const float4*)(&Bs[buf][k][tx * 4]);
                bv[0] = b4.x; bv[1] = b4.y; bv[2] = b4.z; bv[3] = b4.w;
            } else if constexpr (NQ == 2) {
                float2 b2 = *(const float2*)(&Bs[buf][k][tx * 2]);
                bv[0] = b2.x; bv[1] = b2.y;
            } else {
                bv[0] = Bs[buf][k][tx];
            }
#pragma unroll
            for (int i = 0; i < 4; i++)
#pragma unroll
                for (int j = 0; j < NQ; j++)
                    acc[i][j] += av[i] * bv[j];
        }
        if (more) {
            int nb = buf ^ 1;
#pragma unroll
            for (int q = 0; q < 4;  q++) As[nb][kk][rowq + 16*q] = aR[q];
#pragma unroll
            for (int q = 0; q < NQ; q++) Bs[nb][kk][rowq + 16*q] = bR[q];
            __syncthreads();
            buf = nb;
        }
    }

#pragma unroll
    for (int i = 0; i < 4; i++) {
        int m = m0 + ty * 4 + i;
        int p = p0 + tx * NQ;
        int b = p / HoWo; int r = p - b * HoWo;
        float* dst = &out[(size_t)(b * Cout + m) * HoWo + r];
        if constexpr (NQ == 4) {
            *(float4*)dst = make_float4(acc[i][0], acc[i][1], acc[i][2], acc[i][3]);
        } else if constexpr (NQ == 2) {
            *(float2*)dst = make_float2(acc[i][0], acc[i][1]);
        } else {
            dst[0] = acc[i][0];
        }
    }
}

__global__ void __launch_bounds__(256,3) k_conv_d1(const float* __restrict__ w)
{ conv_v15<64,128,128,128,1,64>(g_h0, w, g_h1); }
__global__ void __launch_bounds__(256,3) k_conv_d2(const float* __restrict__ w)
{ conv_v15<128,64,64,256,1,32>(g_h1, w, g_h2); }
__global__ void __launch_bounds__(256,3) k_conv_d3(const float* __restrict__ w)
{ conv_v15<256,32,32,512,1,32>(g_h2, w, g_h3); }
__global__ void __launch_bounds__(256,3) k_conv_d4(const float* __restrict__ w)
{ conv_v15<512,16,16,512,1,16>(g_h3, w, g_h4); }

// ---------------- deconv weight repack (per-parity) ----------------
__global__ void k_repack(const float* __restrict__ w, int Cin, int Cout)
{
    int idx = blockIdx.x * blockDim.x + threadIdx.x;
    int total = 4 * Cout * Cin * 4;
    if (idx >= total) return;
    int t = idx & 3, tmp = idx >> 2;
    int ci = tmp % Cin; tmp /= Cin;
    int m = tmp % Cout;
    int pz = tmp / Cout;
    int py = pz >> 1, px = pz & 1;
    int di = t >> 1, dj = t & 1;
    int ky = py ? (1 + 2*di) : (2*di);
    int kx = px ? (1 + 2*dj) : (2*dj);
    g_wpack[idx] = w[(((size_t)ci * Cout + m) * 4 + (3 - ky)) * 4 + (3 - kx)];
}

// =====================================================================
// transposed conv — v1.5 FFMA (R7 body) + NT template {64,32}
// =====================================================================
template<int Cin, int C1, int Hi, int Wi, int Cout, int NT>
__device__ __forceinline__ void deconv_v15(const float* __restrict__ in1,
                                           const float* __restrict__ in2,
                                           float* __restrict__ out)
{
    constexpr int HiWi = Hi * Wi;
    constexpr int Wo = 2 * Wi;
    constexpr int HoWo = 4 * HiWi;
    constexpr int C2 = Cin - C1;
    constexpr int NCH = Cin / 4;
    constexpr int NQ = NT / 16;
    const int pz = blockIdx.z;
    const int py = pz >> 1, px = pz & 1;
    const int m0 = blockIdx.y * 64;
    const int n0 = blockIdx.x * NT;

    __shared__ __align__(16) float As[2][16][68];
    __shared__ __align__(16) float Bs[2][16][NT + 4];

    const int tid  = threadIdx.x;
    const int kk   = tid & 15;
    const int rowq = tid >> 4;
    const int cil = kk >> 2, t = kk & 3;
    const int di = t >> 1, dj = t & 1;
    const int tx = kk, ty = rowq;

    int woff[4];
#pragma unroll
    for (int q = 0; q < 4; q++)
        woff[q] = ((pz * Cout + m0 + rowq + 16 * q) * Cin + cil) * 4 + t;

    int pixq[NQ], bq[NQ];
#pragma unroll
    for (int q = 0; q < NQ; q++) {
        int n = n0 + rowq + 16 * q;
        int b = n / HiWi; int r = n - b * HiWi;
        int yy = r / Wi;  int xx = r - yy * Wi;
        int i = py ? (yy + di) : (yy - 1 + di);
        int j = px ? (xx + dj) : (xx - 1 + dj);
        bool v = i >= 0 && i < Hi && j >= 0 && j < Wi;
        pixq[q] = v ? (i * Wi + j) : -1;
        bq[q] = b;
    }

    auto ldb = [&](int ci, int q) -> float {
        float v = 0.f;
        if (pixq[q] >= 0) {
            const float* src = (ci < C1)
                ? in1 + (size_t)(bq[q] * C1 + ci) * HiWi
                : in2 + (size_t)(bq[q] * C2 + (ci - C1)) * HiWi;
            v = fmaxf(__ldg(src + pixq[q]), 0.f);
        }
        return v;
    };

    float aR[4], bR[NQ];
#pragma unroll
    for (int q = 0; q < 4;  q++) aR[q] = g_wpack[woff[q]];
#pragma unroll
    for (int q = 0; q < NQ; q++) bR[q] = ldb(cil, q);
#pragma unroll
    for (int q = 0; q < 4;  q++) As[0][kk][rowq + 16*q] = aR[q];
#pragma unroll
    for (int q = 0; q < NQ; q++) Bs[0][kk][rowq + 16*q] = bR[q];
    __syncthreads();

    float acc[4][NQ];
#pragma unroll
    for (int i = 0; i < 4; i++)
#pragma unroll
        for (int j = 0; j < NQ; j++) acc[i][j] = 0.f;

    int buf = 0;
    for (int s = 0; s < NCH; s++) {
        const bool more = (s + 1 < NCH);
        if (more) {
            int ci = 4 * (s + 1) + cil;
#pragma unroll
            for (int q = 0; q < 4;  q++) aR[q] = g_wpack[woff[q] + (s + 1) * 16];
#pragma unroll
            for (int q = 0; q < NQ; q++) bR[q] = ldb(ci, q);
        }
#pragma unroll
        for (int k = 0; k < 16; k++) {
            float4 a4 = *(const float4*)(&As[buf][k][ty * 4]);
            float av[4] = {a4.x, a4.y, a4.z, a4.w};
            float bv[NQ];
            if constexpr (NQ == 4) {
                float4 b4 = *(const float4*)(&Bs[buf][k][tx * 4]);
                bv[0] = b4.x; bv[1] = b4.y; bv[2] = b4.z; bv[3] = b4.w;
            } else if constexpr (NQ == 2) {
                float2 b2 = *(const float2*)(&Bs[buf][k][tx * 2]);
                bv[0] = b2.x; bv[1] = b2.y;
            } else {
                bv[0] = Bs[buf][k][tx];
            }
#pragma unroll
            for (int i = 0; i < 4; i++)
#pragma unroll
                for (int j = 0; j < NQ; j++)
                    acc[i][j] += av[i] * bv[j];
        }
        if (more) {
            int nb = buf ^ 1;
#pragma unroll
            for (int q = 0; q < 4;  q++) As[nb][kk][rowq + 16*q] = aR[q];
#pragma unroll
            for (int q = 0; q < NQ; q++) Bs[nb][kk][rowq + 16*q] = bR[q];
            __syncthreads();
            buf = nb;
        }
    }

#pragma unroll
    for (int i = 0; i < 4; i++) {
        int m = m0 + ty * 4 + i;
#pragma unroll
        for (int j = 0; j < NQ; j++) {
            int n = n0 + tx * NQ + j;
            int b = n / HiWi; int r = n - b * HiWi;
            int yy = r / Wi;  int xx = r - yy * Wi;
            int y = 2 * yy + py, x = 2 * xx + px;
            out[(size_t)(b * Cout + m) * HoWo + y * Wo + x] = acc[i][j];
        }
    }
}

__global__ void __launch_bounds__(256,3) k_deconv_u4()
{ deconv_v15<512,512,8,8,512,32>(g_h4, g_h4, g_u4); }
__global__ void __launch_bounds__(256,3) k_deconv_u3()
{ deconv_v15<1024,512,16,16,256,32>(g_h3, g_u4, g_u3); }
__global__ void __launch_bounds__(256,3) k_deconv_u2()
{ deconv_v15<512,256,32,32,128,64>(g_h2, g_u3, g_u2); }
__global__ void __launch_bounds__(256,3) k_deconv_u1()
{ deconv_v15<256,128,64,64,64,64>(g_h1, g_u2, g_u1); }

// ---------------- batchnorm (R7 pattern: stats then apply) ----------------
template<int C, int HW>
__device__ __forceinline__ void bn_stats_body(const float* __restrict__ x,
                                              const float* __restrict__ g,
                                              const float* __restrict__ bet)
{
    int c = blockIdx.x;
    constexpr int per = BB * HW;
    double s = 0.0, s2 = 0.0;
    for (int i = threadIdx.x; i < per; i += blockDim.x) {
        int bb = i / HW; int r = i - bb * HW;
        float v = x[(size_t)(bb * C + c) * HW + r];
        s += v; s2 += (double)v * (double)v;
    }
    __shared__ double sh1[256], sh2[256];
    int tl = threadIdx.x;
    sh1[tl] = s; sh2[tl] = s2;
    __syncthreads();
    for (int o = 128; o > 0; o >>= 1) {
        if (tl < o) { sh1[tl] += sh1[tl+o]; sh2[tl] += sh2[tl+o]; }
        __syncthreads();
    }
    if (tl == 0) {
        double m = sh1[0] / per;
        double var = sh2[0] / per - m * m;
        float sc = g[c] * (float)(1.0 / sqrt(var + 1e-5));
        g_scale[c] = sc;
        g_shift[c] = bet[c] - (float)m * sc;
    }
}

template<int C, int HW>
__device__ __forceinline__ void bn_apply_body(float* __restrict__ x)
{
    constexpr int total = BB * C * HW;
    int i = blockIdx.x * blockDim.x + threadIdx.x;
    if (i >= total) return;
    int c = (i / HW) % C;
    x[i] = x[i] * g_scale[c] + g_shift[c];
}

__global__ void k_bns_h1(const float* g, const float* b){ bn_stats_body<128,4096>(g_h1,g,b); }
__global__ void k_bna_h1(){ bn_apply_body<128,4096>(g_h1); }
__global__ void k_bns_h2(const float* g, const float* b){ bn_stats_body<256,1024>(g_h2,g,b); }
__global__ void k_bna_h2(){ bn_apply_body<256,1024>(g_h2); }
__global__ void k_bns_h3(const float* g, const float* b){ bn_stats_body<512,256>(g_h3,g,b); }
__global__ void k_bna_h3(){ bn_apply_body<512,256>(g_h3); }
__global__ void k_bns_u4(const float* g, const float* b){ bn_stats_body<512,256>(g_u4,g,b); }
__global__ void k_bna_u4(){ bn_apply_body<512,256>(g_u4); }
__global__ void k_bns_u3(const float* g, const float* b){ bn_stats_body<256,1024>(g_u3,g,b); }
__global__ void k_bna_u3(){ bn_apply_body<256,1024>(g_u3); }
__global__ void k_bns_u2(const float* g, const float* b){ bn_stats_body<128,4096>(g_u2,g,b); }
__global__ void k_bna_u2(){ bn_apply_body<128,4096>(g_u2); }
__global__ void k_bns_u1(const float* g, const float* b){ bn_stats_body<64,16384>(g_u1,g,b); }
__global__ void k_bna_u1(){ bn_apply_body<64,16384>(g_u1); }

// ---------------- final deconv u0: 2x2 quad per thread (R7 body) ------------
__global__ void k_deconv_u0(const float* __restrict__ w,
                            const float* __restrict__ b0,
                            float* __restrict__ out)
{
    __shared__ float ws[2048];
    for (int i = threadIdx.x; i < 2048; i += blockDim.x) ws[i] = w[i];
    __syncthreads();

    int idx = blockIdx.x * blockDim.x + threadIdx.x;
    if (idx >= BB * 128 * 128) return;
    int xx = idx & 127, yy = (idx >> 7) & 127, b = idx >> 14;

    const float* h0p = g_h0 + (size_t)b * 64 * 16384;
    const float* u1p = g_u1 + (size_t)b * 64 * 16384;
    float a00 = 0.f, a01 = 0.f, a10 = 0.f, a11 = 0.f;

    for (int ci = 0; ci < 128; ci++) {
        const float* src = (ci < 64) ? (h0p + ci * 16384) : (u1p + (ci - 64) * 16384);
        float v[3][3];
#pragma unroll
        for (int dy = 0; dy < 3; dy++) {
            int i = yy - 1 + dy;
#pragma unroll
            for (int dxx = 0; dxx < 3; dxx++) {
                int jx = xx - 1 + dxx;
                v[dy][dxx] = (i >= 0 && i < 128 && jx >= 0 && jx < 128)
                             ? fmaxf(__ldg(src + i * 128 + jx), 0.f) : 0.f;
            }
        }
        const float* wsr = ws + ci * 16;
#pragma unroll
        for (int di = 0; di < 2; di++)
#pragma unroll
            for (int dj = 0; dj < 2; dj++)
                a00 += v[di][dj] * wsr[(3 - 2*di) * 4 + (3 - 2*dj)];
#pragma unroll
        for (int di = 0; di < 2; di++)
#pragma unroll
            for (int dj = 0; dj < 2; dj++)
                a01 += v[di][dj+1] * wsr[(3 - 2*di) * 4 + (2 - 2*dj)];
#pragma unroll
        for (int di = 0; di < 2; di++)
#pragma unroll
            for (int dj = 0; dj < 2; dj++)
                a10 += v[di+1][dj] * wsr[(2 - 2*di) * 4 + (3 - 2*dj)];
#pragma unroll
        for (int di = 0; di < 2; di++)
#pragma unroll
            for (int dj = 0; dj < 2; dj++)
                a11 += v[di+1][dj+1] * wsr[(2 - 2*di) * 4 + (2 - 2*dj)];
    }

    float bias = __ldg(&b0[0]);
    int base = b * PIX + (2 * yy) * 256 + 2 * xx;
    out[base]       = 1.0f / (1.0f + expf(-(a00 + bias)));
    out[base + 1]   = 1.0f / (1.0f + expf(-(a01 + bias)));
    out[base + 256] = 1.0f / (1.0f + expf(-(a10 + bias)));
    out[base + 257] = 1.0f / (1.0f + expf(-(a11 + bias)));
}

// ---------------- driver ----------------
extern "C" void kernel_launch(void* const* d_in, const int* in_sizes, int n_in,
                              void* d_out, int out_size)
{
    const float* sig   = (const float*)d_in[0];
    const float* trans = (const float*)d_in[1];
    const float* w_d0  = (const float*)d_in[2];
    const float* w_d1  = (const float*)d_in[3];
    const float* g_d1  = (const float*)d_in[4];
    const float* b_d1  = (const float*)d_in[5];
    const float* w_d2  = (const float*)d_in[6];
    const float* g_d2  = (const float*)d_in[7];
    const float* b_d2  = (const float*)d_in[8];
    const float* w_d3  = (const float*)d_in[9];
    const float* g_d3  = (const float*)d_in[10];
    const float* b_d3  = (const float*)d_in[11];
    const float* w_d4  = (const float*)d_in[12];
    const float* w_u4  = (const float*)d_in[13];
    const float* g_u4p = (const float*)d_in[14];
    const float* b_u4p = (const float*)d_in[15];
    const float* w_u3  = (const float*)d_in[16];
    const float* g_u3p = (const float*)d_in[17];
    const float* b_u3p = (const float*)d_in[18];
    const float* w_u2  = (const float*)d_in[19];
    const float* g_u2p = (const float*)d_in[20];
    const float* b_u2p = (const float*)d_in[21];
    const float* w_u1  = (const float*)d_in[22];
    const float* g_u1p = (const float*)d_in[23];
    const float* b_u1p = (const float*)d_in[24];
    const float* w_u0  = (const float*)d_in[25];
    const float* b_u0  = (const float*)d_in[26];

    float* outp = (float*)d_out;
    float* out_rec = outp + IMG;
    int copy_rec = (out_size >= 2 * IMG) ? 1 : 0;

    k_backproject<<<PIX / 256, 256>>>(sig, trans);
    k_minmax_init<<<1, 1>>>();
    k_minmax_reduce<<<256, 256>>>();
    k_normalize<<<(IMG + 255) / 256, 256>>>(out_rec, copy_rec);

    k_conv_d0<<<1024, 256>>>(w_d0);
    k_conv_d1<<<dim3(1024, 2), 256>>>(w_d1);
    k_bns_h1<<<128, 256>>>(g_d1, b_d1);
    k_bna_h1<<<BB*128*4096/256, 256>>>();
    k_conv_d2<<<dim3(512, 4), 256>>>(w_d2);      // NT=32
    k_bns_h2<<<256, 256>>>(g_d2, b_d2);
    k_bna_h2<<<BB*256*1024/256, 256>>>();
    k_conv_d3<<<dim3(128, 8), 256>>>(w_d3);      // NT=32
    k_bns_h3<<<512, 256>>>(g_d3, b_d3);
    k_bna_h3<<<BB*512*256/256, 256>>>();
    k_conv_d4<<<dim3(64, 8), 256>>>(w_d4);       // NT=16

    k_repack<<<(512*512*16 + 255)/256, 256>>>(w_u4, 512, 512);
    k_deconv_u4<<<dim3(32, 8, 4), 256>>>();      // NT=32
    k_bns_u4<<<512, 256>>>(g_u4p, b_u4p);
    k_bna_u4<<<BB*512*256/256, 256>>>();

    k_repack<<<(1024*256*16 + 255)/256, 256>>>(w_u3, 1024, 256);
    k_deconv_u3<<<dim3(128, 4, 4), 256>>>();     // NT=32
    k_bns_u3<<<256, 256>>>(g_u3p, b_u3p);
    k_bna_u3<<<BB*256*1024/256, 256>>>();

    k_repack<<<(512*128*16 + 255)/256, 256>>>(w_u2, 512, 128);
    k_deconv_u2<<<dim3(256, 2, 4), 256>>>();     // NT=64
    k_bns_u2<<<128, 256>>>(g_u2p, b_u2p);
    k_bna_u2<<<BB*128*4096/256, 256>>>();

    k_repack<<<(256*64*16 + 255)/256, 256>>>(w_u1, 256, 64);
    k_deconv_u1<<<dim3(1024, 1, 4), 256>>>();    // NT=64
    k_bns_u1<<<64, 256>>>(g_u1p, b_u1p);
    k_bna_u1<<<BB*64*16384/256, 256>>>();

    k_deconv_u0<<<(BB*128*128 + 255) / 256, 256>>>(w_u0, b_u0, outp);
}

// round 15
// speedup vs baseline: 1.0724x; 1.0724x over previous
#include <cuda_runtime.h>
#include <math.h>

#define BB   16
#define SS   32
#define NTT  2029
#define NN   256
#define PIX  (NN*NN)
#define IMG  (BB*PIX)

__device__ float g_rec [BB*PIX];
__device__ float g_h0  [BB*64 *128*128];
__device__ float g_h1  [BB*128*64 *64 ];
__device__ float g_h2  [BB*256*32 *32 ];
__device__ float g_h3  [BB*512*16 *16 ];
__device__ float g_h4  [BB*512*8  *8  ];
__device__ float g_u4  [BB*512*16 *16 ];
__device__ float g_u3  [BB*256*32 *32 ];
__device__ float g_u2  [BB*128*64 *64 ];
__device__ float g_u1  [BB*64 *128*128];
__device__ float g_wpack[4*512*512*4];
__device__ float g_mm[2];
__device__ float g_scale[512];
__device__ float g_shift[512];

// ---------------- backprojection (bit-exact passing form — DO NOT TOUCH) -----
__global__ void k_backproject(const float* __restrict__ sig,
                              const float* __restrict__ trans)
{
    int idx = blockIdx.x * blockDim.x + threadIdx.x;
    if (idx >= PIX) return;
    int j = idx & 255, i = idx >> 8;
    const float startf = -0.0125f, stopf = 0.0125f;
    float stepj = __fdiv_rn((float)j, 255.0f);
    float stepi = __fdiv_rn((float)i, 255.0f);
    float cj = __fadd_rn(__fmul_rn(startf, __fsub_rn(1.0f, stepj)), __fmul_rn(stopf, stepj));
    float ci = __fadd_rn(__fmul_rn(startf, __fsub_rn(1.0f, stepi)), __fmul_rn(stopf, stepi));
    float acc[BB];
#pragma unroll
    for (int b = 0; b < BB; b++) acc[b] = 0.f;
    for (int s = 0; s < SS; s++) {
        float dx = __fsub_rn(cj, __ldg(&trans[2*s+0]));
        float dy = __fsub_rn(ci, __ldg(&trans[2*s+1]));
        float dd = __fadd_rn(__fmul_rn(dx, dx), __fmul_rn(dy, dy));
        float d  = __fsqrt_rn(dd);
        float v  = __fadd_rn(__fsub_rn(__fdiv_rn(__fmul_rn(d, 40000000.0f), 1572.0f), 113.0f), 1.0f);
        int t = (int)rintf(v);
        t = max(0, min(t, NTT-1));
        const float* sp = sig + (size_t)t * SS + s;
#pragma unroll
        for (int b = 0; b < BB; b++) acc[b] += __ldg(sp + (size_t)b * NTT * SS);
    }
#pragma unroll
    for (int b = 0; b < BB; b++) g_rec[(size_t)b * PIX + idx] = acc[b] * (1.0f / 32.0f);
}

__device__ void atomicMinF(float* a, float v) {
    int old = __float_as_int(*a);
    while (v < __int_as_float(old)) {
        int prev = atomicCAS((int*)a, old, __float_as_int(v));
        if (prev == old) break; old = prev;
    }
}
__device__ void atomicMaxF(float* a, float v) {
    int old = __float_as_int(*a);
    while (v > __int_as_float(old)) {
        int prev = atomicCAS((int*)a, old, __float_as_int(v));
        if (prev == old) break; old = prev;
    }
}
__global__ void k_minmax_init() { g_mm[0] = INFINITY; g_mm[1] = -INFINITY; }

__global__ void k_minmax_reduce()
{
    float mn = INFINITY, mx = -INFINITY;
    for (int i = blockIdx.x * blockDim.x + threadIdx.x; i < IMG; i += gridDim.x * blockDim.x) {
        float v = g_rec[i]; mn = fminf(mn, v); mx = fmaxf(mx, v);
    }
    __shared__ float smn[256], smx[256];
    int t = threadIdx.x;
    smn[t] = mn; smx[t] = mx;
    __syncthreads();
    for (int o = 128; o > 0; o >>= 1) {
        if (t < o) { smn[t] = fminf(smn[t], smn[t+o]); smx[t] = fmaxf(smx[t], smx[t+o]); }
        __syncthreads();
    }
    if (t == 0) { atomicMinF(&g_mm[0], smn[0]); atomicMaxF(&g_mm[1], smx[0]); }
}

__global__ void k_normalize(float* __restrict__ out_rec, int copy_out)
{
    int i = blockIdx.x * blockDim.x + threadIdx.x;
    if (i >= IMG) return;
    float mn = g_mm[0], mx = g_mm[1];
    float v = __fdiv_rn(__fsub_rn(g_rec[i], mn), __fsub_rn(mx, mn));
    g_rec[i] = v;
    if (copy_out) out_rec[i] = v;
}

// ---------------- conv d0 (Cin=1): direct, taps ascending ----------------
__global__ void __launch_bounds__(256) k_conv_d0(const float* __restrict__ w)
{
    __shared__ float ws[1024];
    for (int i = threadIdx.x; i < 1024; i += 256) ws[i] = w[i];
    __syncthreads();
    int idx = blockIdx.x * 256 + threadIdx.x;        // 16*128*128
    int x = idx & 127, y = (idx >> 7) & 127, b = idx >> 14;
    float patch[16];
#pragma unroll
    for (int t = 0; t < 16; t++) {
        int iy = 2*y - 1 + (t >> 2), ix = 2*x - 1 + (t & 3);
        patch[t] = (iy >= 0 && iy < 256 && ix >= 0 && ix < 256)
                   ? g_rec[b * PIX + iy * 256 + ix] : 0.f;
    }
    float* op = g_h0 + ((size_t)b * 64 << 14) + (y << 7) + x;
    for (int co = 0; co < 64; co++) {
        float a = 0.f;
#pragma unroll
        for (int t = 0; t < 16; t++) a += patch[t] * ws[co * 16 + t];
        op[(size_t)co << 14] = a;
    }
}

// =====================================================================
// conv stride-2 k4 p1 — v1.5 FFMA (R7 body, NT=64 everywhere)
// =====================================================================
template<int Cin, int Hi, int Wi, int Cout, int ACT>
__device__ __forceinline__ void conv_v15(const float* __restrict__ in,
                                         const float* __restrict__ w,
                                         float* __restrict__ out)
{
    constexpr int Ho = Hi >> 1, Wo = Wi >> 1;
    constexpr int HoWo = Ho * Wo;
    constexpr int HiWi = Hi * Wi;
    const int m0 = blockIdx.y * 64;
    const int p0 = blockIdx.x * 64;

    __shared__ __align__(16) float As[2][16][68];
    __shared__ __align__(16) float Bs[2][16][68];

    const int tid  = threadIdx.x;
    const int kk   = tid & 15;
    const int rowq = tid >> 4;
    const int ky = kk >> 2, kx = kk & 3;
    const int tx = kk, ty = rowq;

    int woff[4], bofs[4];
#pragma unroll
    for (int q = 0; q < 4; q++) {
        int n = rowq + 16 * q;
        woff[q] = (m0 + n) * Cin * 16 + kk;
        int p = p0 + n;
        int b = p / HoWo; int r = p - b * HoWo;
        int y = r / Wo;   int x = r - y * Wo;
        int iy = 2*y - 1 + ky, ix = 2*x - 1 + kx;
        bool v = iy >= 0 && iy < Hi && ix >= 0 && ix < Wi;
        bofs[q] = v ? (b * Cin * HiWi + iy * Wi + ix) : -1;
    }

    float aR[4], bR[4];
#pragma unroll
    for (int q = 0; q < 4; q++) {
        aR[q] = __ldg(w + woff[q]);
        float v = 0.f;
        if (bofs[q] >= 0) {
            v = __ldg(in + bofs[q]);
            if (ACT) v = (v >= 0.f) ? v : 0.2f * v;
        }
        bR[q] = v;
    }
#pragma unroll
    for (int q = 0; q < 4; q++) {
        As[0][kk][rowq + 16*q] = aR[q];
        Bs[0][kk][rowq + 16*q] = bR[q];
    }
    __syncthreads();

    float acc[4][4];
#pragma unroll
    for (int i = 0; i < 4; i++)
#pragma unroll
        for (int j = 0; j < 4; j++) acc[i][j] = 0.f;

    int buf = 0;
    for (int cci = 0; cci < Cin; cci++) {
        const bool more = (cci + 1 < Cin);
        if (more) {
            const float* wp = w + (size_t)(cci + 1) * 16;
            const float* ip = in + (size_t)(cci + 1) * HiWi;
#pragma unroll
            for (int q = 0; q < 4; q++) {
                aR[q] = __ldg(wp + woff[q]);
                float v = 0.f;
                if (bofs[q] >= 0) {
                    v = __ldg(ip + bofs[q]);
                    if (ACT) v = (v >= 0.f) ? v : 0.2f * v;
                }
                bR[q] = v;
            }
        }
#pragma unroll
        for (int k = 0; k < 16; k++) {
            float4 a4 = *(const float4*)(&As[buf][k][ty * 4]);
            float4 b4 = *(const float4*)(&Bs[buf][k][tx * 4]);
            float av[4] = {a4.x, a4.y, a4.z, a4.w};
            float bv[4] = {b4.x, b4.y, b4.z, b4.w};
#pragma unroll
            for (int i = 0; i < 4; i++)
#pragma unroll
                for (int j = 0; j < 4; j++)
                    acc[i][j] += av[i] * bv[j];
        }
        if (more) {
            int nb = buf ^ 1;
#pragma unroll
            for (int q = 0; q < 4; q++) {
                As[nb][kk][rowq + 16*q] = aR[q];
                Bs[nb][kk][rowq + 16*q] = bR[q];
            }
            __syncthreads();
            buf = nb;
        }
    }

#pragma unroll
    for (int i = 0; i < 4; i++) {
        int m = m0 + ty * 4 + i;
        int p = p0 + tx * 4;
        int b = p / HoWo; int r = p - b * HoWo;
        float4 v = make_float4(acc[i][0], acc[i][1], acc[i][2], acc[i][3]);
        *(float4*)(&out[(size_t)(b * Cout + m) * HoWo + r]) = v;
    }
}

__global__ void __launch_bounds__(256,3) k_conv_d1(const float* __restrict__ w)
{ conv_v15<64,128,128,128,1>(g_h0, w, g_h1); }
__global__ void __launch_bounds__(256,3) k_conv_d2(const float* __restrict__ w)
{ conv_v15<128,64,64,256,1>(g_h1, w, g_h2); }
__global__ void __launch_bounds__(256,3) k_conv_d3(const float* __restrict__ w)
{ conv_v15<256,32,32,512,1>(g_h2, w, g_h3); }
__global__ void __launch_bounds__(256,3) k_conv_d4(const float* __restrict__ w)
{ conv_v15<512,16,16,512,1>(g_h3, w, g_h4); }

// ---------------- deconv weight repack (per-parity) ----------------
__global__ void k_repack(const float* __restrict__ w, int Cin, int Cout)
{
    int idx = blockIdx.x * blockDim.x + threadIdx.x;
    int total = 4 * Cout * Cin * 4;
    if (idx >= total) return;
    int t = idx & 3, tmp = idx >> 2;
    int ci = tmp % Cin; tmp /= Cin;
    int m = tmp % Cout;
    int pz = tmp / Cout;
    int py = pz >> 1, px = pz & 1;
    int di = t >> 1, dj = t & 1;
    int ky = py ? (1 + 2*di) : (2*di);
    int kx = px ? (1 + 2*dj) : (2*dj);
    g_wpack[idx] = w[(((size_t)ci * Cout + m) * 4 + (3 - ky)) * 4 + (3 - kx)];
}

// =====================================================================
// transposed conv — v1.5 FFMA (R7 body, NT=64)
// =====================================================================
template<int Cin, int C1, int Hi, int Wi, int Cout>
__device__ __forceinline__ void deconv_v15(const float* __restrict__ in1,
                                           const float* __restrict__ in2,
                                           float* __restrict__ out)
{
    constexpr int HiWi = Hi * Wi;
    constexpr int Wo = 2 * Wi;
    constexpr int HoWo = 4 * HiWi;
    constexpr int C2 = Cin - C1;
    constexpr int NCH = Cin / 4;
    const int pz = blockIdx.z;
    const int py = pz >> 1, px = pz & 1;
    const int m0 = blockIdx.y * 64;
    const int n0 = blockIdx.x * 64;

    __shared__ __align__(16) float As[2][16][68];
    __shared__ __align__(16) float Bs[2][16][68];

    const int tid  = threadIdx.x;
    const int kk   = tid & 15;
    const int rowq = tid >> 4;
    const int cil = kk >> 2, t = kk & 3;
    const int di = t >> 1, dj = t & 1;
    const int tx = kk, ty = rowq;

    int woff[4], pixq[4], bq[4];
#pragma unroll
    for (int q = 0; q < 4; q++) {
        int n = n0 + rowq + 16 * q;
        int b = n / HiWi; int r = n - b * HiWi;
        int yy = r / Wi;  int xx = r - yy * Wi;
        int i = py ? (yy + di) : (yy - 1 + di);
        int j = px ? (xx + dj) : (xx - 1 + dj);
        bool v = i >= 0 && i < Hi && j >= 0 && j < Wi;
        pixq[q] = v ? (i * Wi + j) : -1;
        bq[q] = b;
        int m = m0 + rowq + 16 * q;
        woff[q] = ((pz * Cout + m) * Cin + cil) * 4 + t;
    }

    float aR[4], bR[4];
#pragma unroll
    for (int q = 0; q < 4; q++) {
        aR[q] = g_wpack[woff[q]];
        float v = 0.f;
        if (pixq[q] >= 0) {
            const float* src = (cil < C1)
                ? in1 + (size_t)(bq[q] * C1 + cil) * HiWi
                : in2 + (size_t)(bq[q] * C2 + (cil - C1)) * HiWi;
            v = fmaxf(__ldg(src + pixq[q]), 0.f);
        }
        bR[q] = v;
    }
#pragma unroll
    for (int q = 0; q < 4; q++) {
        As[0][kk][rowq + 16*q] = aR[q];
        Bs[0][kk][rowq + 16*q] = bR[q];
    }
    __syncthreads();

    float acc[4][4];
#pragma unroll
    for (int i = 0; i < 4; i++)
#pragma unroll
        for (int j = 0; j < 4; j++) acc[i][j] = 0.f;

    int buf = 0;
    for (int s = 0; s < NCH; s++) {
        const bool more = (s + 1 < NCH);
        if (more) {
            int ci = 4 * (s + 1) + cil;
#pragma unroll
            for (int q = 0; q < 4; q++) {
                aR[q] = g_wpack[woff[q] + (s + 1) * 16];
                float v = 0.f;
                if (pixq[q] >= 0) {
                    const float* src = (ci < C1)
                        ? in1 + (size_t)(bq[q] * C1 + ci) * HiWi
                        : in2 + (size_t)(bq[q] * C2 + (ci - C1)) * HiWi;
                    v = fmaxf(__ldg(src + pixq[q]), 0.f);
                }
                bR[q] = v;
            }
        }
#pragma unroll
        for (int k = 0; k < 16; k++) {
            float4 a4 = *(const float4*)(&As[buf][k][ty * 4]);
            float4 b4 = *(const float4*)(&Bs[buf][k][tx * 4]);
            float av[4] = {a4.x, a4.y, a4.z, a4.w};
            float bv[4] = {b4.x, b4.y, b4.z, b4.w};
#pragma unroll
            for (int i = 0; i < 4; i++)
#pragma unroll
                for (int j = 0; j < 4; j++)
                    acc[i][j] += av[i] * bv[j];
        }
        if (more) {
            int nb = buf ^ 1;
#pragma unroll
            for (int q = 0; q < 4; q++) {
                As[nb][kk][rowq + 16*q] = aR[q];
                Bs[nb][kk][rowq + 16*q] = bR[q];
            }
            __syncthreads();
            buf = nb;
        }
    }

#pragma unroll
    for (int i = 0; i < 4; i++) {
        int m = m0 + ty * 4 + i;
#pragma unroll
        for (int j = 0; j < 4; j++) {
            int n = n0 + tx * 4 + j;
            int b = n / HiWi; int r = n - b * HiWi;
            int yy = r / Wi;  int xx = r - yy * Wi;
            int y = 2 * yy + py, x = 2 * xx + px;
            out[(size_t)(b * Cout + m) * HoWo + y * Wo + x] = acc[i][j];
        }
    }
}

__global__ void __launch_bounds__(256,3) k_deconv_u4()
{ deconv_v15<512,512,8,8,512>(g_h4, g_h4, g_u4); }
__global__ void __launch_bounds__(256,3) k_deconv_u3()
{ deconv_v15<1024,512,16,16,256>(g_h3, g_u4, g_u3); }
__global__ void __launch_bounds__(256,3) k_deconv_u2()
{ deconv_v15<512,256,32,32,128>(g_h2, g_u3, g_u2); }
__global__ void __launch_bounds__(256,3) k_deconv_u1()
{ deconv_v15<256,128,64,64,64>(g_h1, g_u2, g_u1); }

// ---------------- batchnorm (R7 pattern: stats then apply) ----------------
template<int C, int HW>
__device__ __forceinline__ void bn_stats_body(const float* __restrict__ x,
                                              const float* __restrict__ g,
                                              const float* __restrict__ bet)
{
    int c = blockIdx.x;
    constexpr int per = BB * HW;
    double s = 0.0, s2 = 0.0;
    for (int i = threadIdx.x; i < per; i += blockDim.x) {
        int bb = i / HW; int r = i - bb * HW;
        float v = x[(size_t)(bb * C + c) * HW + r];
        s += v; s2 += (double)v * (double)v;
    }
    __shared__ double sh1[256], sh2[256];
    int tl = threadIdx.x;
    sh1[tl] = s; sh2[tl] = s2;
    __syncthreads();
    for (int o = 128; o > 0; o >>= 1) {
        if (tl < o) { sh1[tl] += sh1[tl+o]; sh2[tl] += sh2[tl+o]; }
        __syncthreads();
    }
    if (tl == 0) {
        double m = sh1[0] / per;
        double var = sh2[0] / per - m * m;
        float sc = g[c] * (float)(1.0 / sqrt(var + 1e-5));
        g_scale[c] = sc;
        g_shift[c] = bet[c] - (float)m * sc;
    }
}

template<int C, int HW>
__device__ __forceinline__ void bn_apply_body(float* __restrict__ x)
{
    constexpr int total = BB * C * HW;
    int i = blockIdx.x * blockDim.x + threadIdx.x;
    if (i >= total) return;
    int c = (i / HW) % C;
    x[i] = x[i] * g_scale[c] + g_shift[c];
}

__global__ void k_bns_h1(const float* g, const float* b){ bn_stats_body<128,4096>(g_h1,g,b); }
__global__ void k_bna_h1(){ bn_apply_body<128,4096>(g_h1); }
__global__ void k_bns_h2(const float* g, const float* b){ bn_stats_body<256,1024>(g_h2,g,b); }
__global__ void k_bna_h2(){ bn_apply_body<256,1024>(g_h2); }
__global__ void k_bns_h3(const float* g, const float* b){ bn_stats_body<512,256>(g_h3,g,b); }
__global__ void k_bna_h3(){ bn_apply_body<512,256>(g_h3); }
__global__ void k_bns_u4(const float* g, const float* b){ bn_stats_body<512,256>(g_u4,g,b); }
__global__ void k_bna_u4(){ bn_apply_body<512,256>(g_u4); }
__global__ void k_bns_u3(const float* g, const float* b){ bn_stats_body<256,1024>(g_u3,g,b); }
__global__ void k_bna_u3(){ bn_apply_body<256,1024>(g_u3); }
__global__ void k_bns_u2(const float* g, const float* b){ bn_stats_body<128,4096>(g_u2,g,b); }
__global__ void k_bna_u2(){ bn_apply_body<128,4096>(g_u2); }
__global__ void k_bns_u1(const float* g, const float* b){ bn_stats_body<64,16384>(g_u1,g,b); }
__global__ void k_bna_u1(){ bn_apply_body<64,16384>(g_u1); }

// ---------------- final deconv u0: smem-tiled 2x2 quad per thread ------------
// Block = 16x16 quads (32x32 output pixels). Per ci: 18x18 input neighborhood
// staged in smem (relu'd, zero-padded), then identical FMA chains as R7.
__global__ void __launch_bounds__(256) k_deconv_u0(const float* __restrict__ w,
                                                   const float* __restrict__ b0,
                                                   float* __restrict__ out)
{
    __shared__ float ws[2048];
    __shared__ float tile[18][19];
    const int tid = threadIdx.x;
    for (int i = tid; i < 2048; i += 256) ws[i] = w[i];

    const int blk = blockIdx.x;          // 16 b * 64 tiles
    const int b   = blk >> 6;
    const int tqy = (blk >> 3) & 7;
    const int tqx = blk & 7;
    const int ty  = tid >> 4, tx = tid & 15;
    const int qy  = tqy * 16 + ty;       // quad coords in [0,128)
    const int qx  = tqx * 16 + tx;
    const int gy0 = tqy * 16 - 1;        // tile origin in input coords
    const int gx0 = tqx * 16 - 1;

    const float* h0p = g_h0 + (size_t)b * 64 * 16384;
    const float* u1p = g_u1 + (size_t)b * 64 * 16384;
    float a00 = 0.f, a01 = 0.f, a10 = 0.f, a11 = 0.f;

    for (int ci = 0; ci < 128; ci++) {
        const float* src = (ci < 64) ? (h0p + ci * 16384) : (u1p + (ci - 64) * 16384);
        __syncthreads();   // previous iteration's reads done (also covers ws on ci=0)
#pragma unroll
        for (int i = tid; i < 324; i += 256) {
            int ry = i / 18, rx = i - ry * 18;
            int gy = gy0 + ry, gx = gx0 + rx;
            float v = 0.f;
            if (gy >= 0 && gy < 128 && gx >= 0 && gx < 128)
                v = fmaxf(__ldg(src + gy * 128 + gx), 0.f);
            tile[ry][rx] = v;
        }
        __syncthreads();

        // local neighborhood: v[dy][dxx] = tile[ty+dy][tx+dxx]
        float v[3][3];
#pragma unroll
        for (int dy = 0; dy < 3; dy++)
#pragma unroll
            for (int dxx = 0; dxx < 3; dxx++)
                v[dy][dxx] = tile[ty + dy][tx + dxx];

        const float* wsr = ws + ci * 16;
#pragma unroll
        for (int di = 0; di < 2; di++)
#pragma unroll
            for (int dj = 0; dj < 2; dj++)
                a00 += v[di][dj] * wsr[(3 - 2*di) * 4 + (3 - 2*dj)];
#pragma unroll
        for (int di = 0; di < 2; di++)
#pragma unroll
            for (int dj = 0; dj < 2; dj++)
                a01 += v[di][dj+1] * wsr[(3 - 2*di) * 4 + (2 - 2*dj)];
#pragma unroll
        for (int di = 0; di < 2; di++)
#pragma unroll
            for (int dj = 0; dj < 2; dj++)
                a10 += v[di+1][dj] * wsr[(2 - 2*di) * 4 + (3 - 2*dj)];
#pragma unroll
        for (int di = 0; di < 2; di++)
#pragma unroll
            for (int dj = 0; dj < 2; dj++)
                a11 += v[di+1][dj+1] * wsr[(2 - 2*di) * 4 + (2 - 2*dj)];
    }

    float bias = __ldg(&b0[0]);
    int base = b * PIX + (2 * qy) * 256 + 2 * qx;
    out[base]       = 1.0f / (1.0f + expf(-(a00 + bias)));
    out[base + 1]   = 1.0f / (1.0f + expf(-(a01 + bias)));
    out[base + 256] = 1.0f / (1.0f + expf(-(a10 + bias)));
    out[base + 257] = 1.0f / (1.0f + expf(-(a11 + bias)));
}

// ---------------- driver ----------------
extern "C" void kernel_launch(void* const* d_in, const int* in_sizes, int n_in,
                              void* d_out, int out_size)
{
    const float* sig   = (const float*)d_in[0];
    const float* trans = (const float*)d_in[1];
    const float* w_d0  = (const float*)d_in[2];
    const float* w_d1  = (const float*)d_in[3];
    const float* g_d1  = (const float*)d_in[4];
    const float* b_d1  = (const float*)d_in[5];
    const float* w_d2  = (const float*)d_in[6];
    const float* g_d2  = (const float*)d_in[7];
    const float* b_d2  = (const float*)d_in[8];
    const float* w_d3  = (const float*)d_in[9];
    const float* g_d3  = (const float*)d_in[10];
    const float* b_d3  = (const float*)d_in[11];
    const float* w_d4  = (const float*)d_in[12];
    const float* w_u4  = (const float*)d_in[13];
    const float* g_u4p = (const float*)d_in[14];
    const float* b_u4p = (const float*)d_in[15];
    const float* w_u3  = (const float*)d_in[16];
    const float* g_u3p = (const float*)d_in[17];
    const float* b_u3p = (const float*)d_in[18];
    const float* w_u2  = (const float*)d_in[19];
    const float* g_u2p = (const float*)d_in[20];
    const float* b_u2p = (const float*)d_in[21];
    const float* w_u1  = (const float*)d_in[22];
    const float* g_u1p = (const float*)d_in[23];
    const float* b_u1p = (const float*)d_in[24];
    const float* w_u0  = (const float*)d_in[25];
    const float* b_u0  = (const float*)d_in[26];

    float* outp = (float*)d_out;
    float* out_rec = outp + IMG;
    int copy_rec = (out_size >= 2 * IMG) ? 1 : 0;

    k_backproject<<<PIX / 256, 256>>>(sig, trans);
    k_minmax_init<<<1, 1>>>();
    k_minmax_reduce<<<256, 256>>>();
    k_normalize<<<(IMG + 255) / 256, 256>>>(out_rec, copy_rec);

    k_conv_d0<<<1024, 256>>>(w_d0);
    k_conv_d1<<<dim3(1024, 2), 256>>>(w_d1);
    k_bns_h1<<<128, 256>>>(g_d1, b_d1);
    k_bna_h1<<<BB*128*4096/256, 256>>>();
    k_conv_d2<<<dim3(256, 4), 256>>>(w_d2);
    k_bns_h2<<<256, 256>>>(g_d2, b_d2);
    k_bna_h2<<<BB*256*1024/256, 256>>>();
    k_conv_d3<<<dim3(64, 8), 256>>>(w_d3);
    k_bns_h3<<<512, 256>>>(g_d3, b_d3);
    k_bna_h3<<<BB*512*256/256, 256>>>();
    k_conv_d4<<<dim3(16, 8), 256>>>(w_d4);

    k_repack<<<(512*512*16 + 255)/256, 256>>>(w_u4, 512, 512);
    k_deconv_u4<<<dim3(16, 8, 4), 256>>>();
    k_bns_u4<<<512, 256>>>(g_u4p, b_u4p);
    k_bna_u4<<<BB*512*256/256, 256>>>();

    k_repack<<<(1024*256*16 + 255)/256, 256>>>(w_u3, 1024, 256);
    k_deconv_u3<<<dim3(64, 4, 4), 256>>>();
    k_bns_u3<<<256, 256>>>(g_u3p, b_u3p);
    k_bna_u3<<<BB*256*1024/256, 256>>>();

    k_repack<<<(512*128*16 + 255)/256, 256>>>(w_u2, 512, 128);
    k_deconv_u2<<<dim3(256, 2, 4), 256>>>();
    k_bns_u2<<<128, 256>>>(g_u2p, b_u2p);
    k_bna_u2<<<BB*128*4096/256, 256>>>();

    k_repack<<<(256*64*16 + 255)/256, 256>>>(w_u1, 256, 64);
    k_deconv_u1<<<dim3(1024, 1, 4), 256>>>();
    k_bns_u1<<<64, 256>>>(g_u1p, b_u1p);
    k_bna_u1<<<BB*64*16384/256, 256>>>();

    k_deconv_u0<<<1024, 256>>>(w_u0, b_u0, outp);
}

// round 16
// speedup vs baseline: 1.1126x; 1.0374x over previous
#include <cuda_runtime.h>
#include <math.h>

#define BB   16
#define SS   32
#define NTT  2029
#define NN   256
#define PIX  (NN*NN)
#define IMG  (BB*PIX)

__device__ float g_rec [BB*PIX];
__device__ float g_h0  [BB*64 *128*128];
__device__ float g_h1  [BB*128*64 *64 ];
__device__ float g_h2  [BB*256*32 *32 ];
__device__ float g_h3  [BB*512*16 *16 ];
__device__ float g_h4  [BB*512*8  *8  ];
__device__ float g_u4  [BB*512*16 *16 ];
__device__ float g_u3  [BB*256*32 *32 ];
__device__ float g_u2  [BB*128*64 *64 ];
__device__ float g_u1  [BB*64 *128*128];
__device__ float g_wpack[4*512*512*4];
__device__ float g_mm[2];
__device__ float g_scale[512];
__device__ float g_shift[512];

// ---------------- backprojection (bit-exact passing form — DO NOT TOUCH) -----
__global__ void k_backproject(const float* __restrict__ sig,
                              const float* __restrict__ trans)
{
    int idx = blockIdx.x * blockDim.x + threadIdx.x;
    if (idx >= PIX) return;
    int j = idx & 255, i = idx >> 8;
    const float startf = -0.0125f, stopf = 0.0125f;
    float stepj = __fdiv_rn((float)j, 255.0f);
    float stepi = __fdiv_rn((float)i, 255.0f);
    float cj = __fadd_rn(__fmul_rn(startf, __fsub_rn(1.0f, stepj)), __fmul_rn(stopf, stepj));
    float ci = __fadd_rn(__fmul_rn(startf, __fsub_rn(1.0f, stepi)), __fmul_rn(stopf, stepi));
    float acc[BB];
#pragma unroll
    for (int b = 0; b < BB; b++) acc[b] = 0.f;
    for (int s = 0; s < SS; s++) {
        float dx = __fsub_rn(cj, __ldg(&trans[2*s+0]));
        float dy = __fsub_rn(ci, __ldg(&trans[2*s+1]));
        float dd = __fadd_rn(__fmul_rn(dx, dx), __fmul_rn(dy, dy));
        float d  = __fsqrt_rn(dd);
        float v  = __fadd_rn(__fsub_rn(__fdiv_rn(__fmul_rn(d, 40000000.0f), 1572.0f), 113.0f), 1.0f);
        int t = (int)rintf(v);
        t = max(0, min(t, NTT-1));
        const float* sp = sig + (size_t)t * SS + s;
#pragma unroll
        for (int b = 0; b < BB; b++) acc[b] += __ldg(sp + (size_t)b * NTT * SS);
    }
#pragma unroll
    for (int b = 0; b < BB; b++) g_rec[(size_t)b * PIX + idx] = acc[b] * (1.0f / 32.0f);
}

__device__ void atomicMinF(float* a, float v) {
    int old = __float_as_int(*a);
    while (v < __int_as_float(old)) {
        int prev = atomicCAS((int*)a, old, __float_as_int(v));
        if (prev == old) break; old = prev;
    }
}
__device__ void atomicMaxF(float* a, float v) {
    int old = __float_as_int(*a);
    while (v > __int_as_float(old)) {
        int prev = atomicCAS((int*)a, old, __float_as_int(v));
        if (prev == old) break; old = prev;
    }
}
__global__ void k_minmax_init() { g_mm[0] = INFINITY; g_mm[1] = -INFINITY; }

__global__ void k_minmax_reduce()
{
    float mn = INFINITY, mx = -INFINITY;
    for (int i = blockIdx.x * blockDim.x + threadIdx.x; i < IMG; i += gridDim.x * blockDim.x) {
        float v = g_rec[i]; mn = fminf(mn, v); mx = fmaxf(mx, v);
    }
    __shared__ float smn[256], smx[256];
    int t = threadIdx.x;
    smn[t] = mn; smx[t] = mx;
    __syncthreads();
    for (int o = 128; o > 0; o >>= 1) {
        if (t < o) { smn[t] = fminf(smn[t], smn[t+o]); smx[t] = fmaxf(smx[t], smx[t+o]); }
        __syncthreads();
    }
    if (t == 0) { atomicMinF(&g_mm[0], smn[0]); atomicMaxF(&g_mm[1], smx[0]); }
}

__global__ void k_normalize(float* __restrict__ out_rec, int copy_out)
{
    int i = blockIdx.x * blockDim.x + threadIdx.x;
    if (i >= IMG) return;
    float mn = g_mm[0], mx = g_mm[1];
    float v = __fdiv_rn(__fsub_rn(g_rec[i], mn), __fsub_rn(mx, mn));
    g_rec[i] = v;
    if (copy_out) out_rec[i] = v;
}

// ---------------- conv d0 (Cin=1): direct, taps ascending ----------------
__global__ void __launch_bounds__(256) k_conv_d0(const float* __restrict__ w)
{
    __shared__ float ws[1024];
    for (int i = threadIdx.x; i < 1024; i += 256) ws[i] = w[i];
    __syncthreads();
    int idx = blockIdx.x * 256 + threadIdx.x;        // 16*128*128
    int x = idx & 127, y = (idx >> 7) & 127, b = idx >> 14;
    float patch[16];
#pragma unroll
    for (int t = 0; t < 16; t++) {
        int iy = 2*y - 1 + (t >> 2), ix = 2*x - 1 + (t & 3);
        patch[t] = (iy >= 0 && iy < 256 && ix >= 0 && ix < 256)
                   ? g_rec[b * PIX + iy * 256 + ix] : 0.f;
    }
    float* op = g_h0 + ((size_t)b * 64 << 14) + (y << 7) + x;
    for (int co = 0; co < 64; co++) {
        float a = 0.f;
#pragma unroll
        for (int t = 0; t < 16; t++) a += patch[t] * ws[co * 16 + t];
        op[(size_t)co << 14] = a;
    }
}

// =====================================================================
// conv stride-2 k4 p1 — v1.6: R7 body with K-chunk 32 (2 cci per chunk)
// Per-output accumulation order identical to R7 (cci asc, taps inner).
// =====================================================================
template<int Cin, int Hi, int Wi, int Cout, int ACT>
__device__ __forceinline__ void conv_k32(const float* __restrict__ in,
                                         const float* __restrict__ w,
                                         float* __restrict__ out)
{
    constexpr int Ho = Hi >> 1, Wo = Wi >> 1;
    constexpr int HoWo = Ho * Wo;
    constexpr int HiWi = Hi * Wi;
    constexpr int NCH = Cin / 2;
    const int m0 = blockIdx.y * 64;
    const int p0 = blockIdx.x * 64;

    __shared__ __align__(16) float As[2][32][68];
    __shared__ __align__(16) float Bs[2][32][68];

    const int tid  = threadIdx.x;
    const int kk   = tid & 15;
    const int rowq = tid >> 4;
    const int ky = kk >> 2, kx = kk & 3;
    const int tx = kk, ty = rowq;

    int woff[4], bofs[4];
#pragma unroll
    for (int q = 0; q < 4; q++) {
        int n = rowq + 16 * q;
        woff[q] = (m0 + n) * Cin * 16 + kk;
        int p = p0 + n;
        int b = p / HoWo; int r = p - b * HoWo;
        int y = r / Wo;   int x = r - y * Wo;
        int iy = 2*y - 1 + ky, ix = 2*x - 1 + kx;
        bool v = iy >= 0 && iy < Hi && ix >= 0 && ix < Wi;
        bofs[q] = v ? (b * Cin * HiWi + iy * Wi + ix) : -1;
    }

    float aR[2][4], bR[2][4];
    auto stage = [&](int cci0) {
#pragma unroll
        for (int cl = 0; cl < 2; cl++) {
            const float* wp = w + (size_t)(cci0 + cl) * 16;
            const float* ip = in + (size_t)(cci0 + cl) * HiWi;
#pragma unroll
            for (int q = 0; q < 4; q++) {
                aR[cl][q] = __ldg(wp + woff[q]);
                float v = 0.f;
                if (bofs[q] >= 0) {
                    v = __ldg(ip + bofs[q]);
                    if (ACT) v = (v >= 0.f) ? v : 0.2f * v;
                }
                bR[cl][q] = v;
            }
        }
    };
    auto commit = [&](int buf) {
#pragma unroll
        for (int cl = 0; cl < 2; cl++)
#pragma unroll
            for (int q = 0; q < 4; q++) {
                As[buf][cl*16 + kk][rowq + 16*q] = aR[cl][q];
                Bs[buf][cl*16 + kk][rowq + 16*q] = bR[cl][q];
            }
    };

    stage(0); commit(0);
    __syncthreads();

    float acc[4][4];
#pragma unroll
    for (int i = 0; i < 4; i++)
#pragma unroll
        for (int j = 0; j < 4; j++) acc[i][j] = 0.f;

    int buf = 0;
    for (int ch = 0; ch < NCH; ch++) {
        const bool more = (ch + 1 < NCH);
        if (more) stage(2 * (ch + 1));
#pragma unroll
        for (int k = 0; k < 32; k++) {
            float4 a4 = *(const float4*)(&As[buf][k][ty * 4]);
            float4 b4 = *(const float4*)(&Bs[buf][k][tx * 4]);
            float av[4] = {a4.x, a4.y, a4.z, a4.w};
            float bv[4] = {b4.x, b4.y, b4.z, b4.w};
#pragma unroll
            for (int i = 0; i < 4; i++)
#pragma unroll
                for (int j = 0; j < 4; j++)
                    acc[i][j] += av[i] * bv[j];
        }
        if (more) {
            int nb = buf ^ 1;
            commit(nb);
            __syncthreads();
            buf = nb;
        }
    }

#pragma unroll
    for (int i = 0; i < 4; i++) {
        int m = m0 + ty * 4 + i;
        int p = p0 + tx * 4;
        int b = p / HoWo; int r = p - b * HoWo;
        float4 v = make_float4(acc[i][0], acc[i][1], acc[i][2], acc[i][3]);
        *(float4*)(&out[(size_t)(b * Cout + m) * HoWo + r]) = v;
    }
}

__global__ void __launch_bounds__(256,3) k_conv_d1(const float* __restrict__ w)
{ conv_k32<64,128,128,128,1>(g_h0, w, g_h1); }
__global__ void __launch_bounds__(256,3) k_conv_d2(const float* __restrict__ w)
{ conv_k32<128,64,64,256,1>(g_h1, w, g_h2); }
__global__ void __launch_bounds__(256,3) k_conv_d3(const float* __restrict__ w)
{ conv_k32<256,32,32,512,1>(g_h2, w, g_h3); }
__global__ void __launch_bounds__(256,3) k_conv_d4(const float* __restrict__ w)
{ conv_k32<512,16,16,512,1>(g_h3, w, g_h4); }

// ---------------- deconv weight repack (per-parity) ----------------
__global__ void k_repack(const float* __restrict__ w, int Cin, int Cout)
{
    int idx = blockIdx.x * blockDim.x + threadIdx.x;
    int total = 4 * Cout * Cin * 4;
    if (idx >= total) return;
    int t = idx & 3, tmp = idx >> 2;
    int ci = tmp % Cin; tmp /= Cin;
    int m = tmp % Cout;
    int pz = tmp / Cout;
    int py = pz >> 1, px = pz & 1;
    int di = t >> 1, dj = t & 1;
    int ky = py ? (1 + 2*di) : (2*di);
    int kx = px ? (1 + 2*dj) : (2*dj);
    g_wpack[idx] = w[(((size_t)ci * Cout + m) * 4 + (3 - ky)) * 4 + (3 - kx)];
}

// =====================================================================
// transposed conv — v1.6: R7 body with K-chunk 32 (8 ci per chunk)
// =====================================================================
template<int Cin, int C1, int Hi, int Wi, int Cout>
__device__ __forceinline__ void deconv_k32(const float* __restrict__ in1,
                                           const float* __restrict__ in2,
                                           float* __restrict__ out)
{
    constexpr int HiWi = Hi * Wi;
    constexpr int Wo = 2 * Wi;
    constexpr int HoWo = 4 * HiWi;
    constexpr int C2 = Cin - C1;
    constexpr int NCH = Cin / 8;
    const int pz = blockIdx.z;
    const int py = pz >> 1, px = pz & 1;
    const int m0 = blockIdx.y * 64;
    const int n0 = blockIdx.x * 64;

    __shared__ __align__(16) float As[2][32][68];
    __shared__ __align__(16) float Bs[2][32][68];

    const int tid  = threadIdx.x;
    const int kk   = tid & 15;
    const int rowq = tid >> 4;
    const int cil = kk >> 2, t = kk & 3;
    const int di = t >> 1, dj = t & 1;
    const int tx = kk, ty = rowq;

    int woff[4], pixq[4], bq[4];
#pragma unroll
    for (int q = 0; q < 4; q++) {
        int n = n0 + rowq + 16 * q;
        int b = n / HiWi; int r = n - b * HiWi;
        int yy = r / Wi;  int xx = r - yy * Wi;
        int i = py ? (yy + di) : (yy - 1 + di);
        int j = px ? (xx + dj) : (xx - 1 + dj);
        bool v = i >= 0 && i < Hi && j >= 0 && j < Wi;
        pixq[q] = v ? (i * Wi + j) : -1;
        bq[q] = b;
        int m = m0 + rowq + 16 * q;
        woff[q] = ((pz * Cout + m) * Cin + cil) * 4 + t;
    }

    float aR[2][4], bR[2][4];
    auto stage = [&](int ch) {
#pragma unroll
        for (int cl = 0; cl < 2; cl++) {
            int ci = 8 * ch + 4 * cl + cil;
#pragma unroll
            for (int q = 0; q < 4; q++) {
                aR[cl][q] = g_wpack[woff[q] + (2 * ch + cl) * 16];
                float v = 0.f;
                if (pixq[q] >= 0) {
                    const float* src = (ci < C1)
                        ? in1 + (size_t)(bq[q] * C1 + ci) * HiWi
                        : in2 + (size_t)(bq[q] * C2 + (ci - C1)) * HiWi;
                    v = fmaxf(__ldg(src + pixq[q]), 0.f);
                }
                bR[cl][q] = v;
            }
        }
    };
    auto commit = [&](int buf) {
#pragma unroll
        for (int cl = 0; cl < 2; cl++)
#pragma unroll
            for (int q = 0; q < 4; q++) {
                As[buf][cl*16 + kk][rowq + 16*q] = aR[cl][q];
                Bs[buf][cl*16 + kk][rowq + 16*q] = bR[cl][q];
            }
    };

    stage(0); commit(0);
    __syncthreads();

    float acc[4][4];
#pragma unroll
    for (int i = 0; i < 4; i++)
#pragma unroll
        for (int j = 0; j < 4; j++) acc[i][j] = 0.f;

    int buf = 0;
    for (int ch = 0; ch < NCH; ch++) {
        const bool more = (ch + 1 < NCH);
        if (more) stage(ch + 1);
#pragma unroll
        for (int k = 0; k < 32; k++) {
            float4 a4 = *(const float4*)(&As[buf][k][ty * 4]);
            float4 b4 = *(const float4*)(&Bs[buf][k][tx * 4]);
            float av[4] = {a4.x, a4.y, a4.z, a4.w};
            float bv[4] = {b4.x, b4.y, b4.z, b4.w};
#pragma unroll
            for (int i = 0; i < 4; i++)
#pragma unroll
                for (int j = 0; j < 4; j++)
                    acc[i][j] += av[i] * bv[j];
        }
        if (more) {
            int nb = buf ^ 1;
            commit(nb);
            __syncthreads();
            buf = nb;
        }
    }

#pragma unroll
    for (int i = 0; i < 4; i++) {
        int m = m0 + ty * 4 + i;
#pragma unroll
        for (int j = 0; j < 4; j++) {
            int n = n0 + tx * 4 + j;
            int b = n / HiWi; int r = n - b * HiWi;
            int yy = r / Wi;  int xx = r - yy * Wi;
            int y = 2 * yy + py, x = 2 * xx + px;
            out[(size_t)(b * Cout + m) * HoWo + y * Wo + x] = acc[i][j];
        }
    }
}

__global__ void __launch_bounds__(256,3) k_deconv_u4()
{ deconv_k32<512,512,8,8,512>(g_h4, g_h4, g_u4); }
__global__ void __launch_bounds__(256,3) k_deconv_u3()
{ deconv_k32<1024,512,16,16,256>(g_h3, g_u4, g_u3); }
__global__ void __launch_bounds__(256,3) k_deconv_u2()
{ deconv_k32<512,256,32,32,128>(g_h2, g_u3, g_u2); }
__global__ void __launch_bounds__(256,3) k_deconv_u1()
{ deconv_k32<256,128,64,64,64>(g_h1, g_u2, g_u1); }

// ---------------- batchnorm (R7 pattern: stats then apply) ----------------
template<int C, int HW>
__device__ __forceinline__ void bn_stats_body(const float* __restrict__ x,
                                              const float* __restrict__ g,
                                              const float* __restrict__ bet)
{
    int c = blockIdx.x;
    constexpr int per = BB * HW;
    double s = 0.0, s2 = 0.0;
    for (int i = threadIdx.x; i < per; i += blockDim.x) {
        int bb = i / HW; int r = i - bb * HW;
        float v = x[(size_t)(bb * C + c) * HW + r];
        s += v; s2 += (double)v * (double)v;
    }
    __shared__ double sh1[256], sh2[256];
    int tl = threadIdx.x;
    sh1[tl] = s; sh2[tl] = s2;
    __syncthreads();
    for (int o = 128; o > 0; o >>= 1) {
        if (tl < o) { sh1[tl] += sh1[tl+o]; sh2[tl] += sh2[tl+o]; }
        __syncthreads();
    }
    if (tl == 0) {
        double m = sh1[0] / per;
        double var = sh2[0] / per - m * m;
        float sc = g[c] * (float)(1.0 / sqrt(var + 1e-5));
        g_scale[c] = sc;
        g_shift[c] = bet[c] - (float)m * sc;
    }
}

template<int C, int HW>
__device__ __forceinline__ void bn_apply_body(float* __restrict__ x)
{
    constexpr int total = BB * C * HW;
    int i = blockIdx.x * blockDim.x + threadIdx.x;
    if (i >= total) return;
    int c = (i / HW) % C;
    x[i] = x[i] * g_scale[c] + g_shift[c];
}

__global__ void k_bns_h1(const float* g, const float* b){ bn_stats_body<128,4096>(g_h1,g,b); }
__global__ void k_bna_h1(){ bn_apply_body<128,4096>(g_h1); }
__global__ void k_bns_h2(const float* g, const float* b){ bn_stats_body<256,1024>(g_h2,g,b); }
__global__ void k_bna_h2(){ bn_apply_body<256,1024>(g_h2); }
__global__ void k_bns_h3(const float* g, const float* b){ bn_stats_body<512,256>(g_h3,g,b); }
__global__ void k_bna_h3(){ bn_apply_body<512,256>(g_h3); }
__global__ void k_bns_u4(const float* g, const float* b){ bn_stats_body<512,256>(g_u4,g,b); }
__global__ void k_bna_u4(){ bn_apply_body<512,256>(g_u4); }
__global__ void k_bns_u3(const float* g, const float* b){ bn_stats_body<256,1024>(g_u3,g,b); }
__global__ void k_bna_u3(){ bn_apply_body<256,1024>(g_u3); }
__global__ void k_bns_u2(const float* g, const float* b){ bn_stats_body<128,4096>(g_u2,g,b); }
__global__ void k_bna_u2(){ bn_apply_body<128,4096>(g_u2); }
__global__ void k_bns_u1(const float* g, const float* b){ bn_stats_body<64,16384>(g_u1,g,b); }
__global__ void k_bna_u1(){ bn_apply_body<64,16384>(g_u1); }

// ---------------- final deconv u0: 2x2 quad per thread (R7 body) ------------
__global__ void k_deconv_u0(const float* __restrict__ w,
                            const float* __restrict__ b0,
                            float* __restrict__ out)
{
    __shared__ float ws[2048];
    for (int i = threadIdx.x; i < 2048; i += blockDim.x) ws[i] = w[i];
    __syncthreads();

    int idx = blockIdx.x * blockDim.x + threadIdx.x;
    if (idx >= BB * 128 * 128) return;
    int xx = idx & 127, yy = (idx >> 7) & 127, b = idx >> 14;

    const float* h0p = g_h0 + (size_t)b * 64 * 16384;
    const float* u1p = g_u1 + (size_t)b * 64 * 16384;
    float a00 = 0.f, a01 = 0.f, a10 = 0.f, a11 = 0.f;

    for (int ci = 0; ci < 128; ci++) {
        const float* src = (ci < 64) ? (h0p + ci * 16384) : (u1p + (ci - 64) * 16384);
        float v[3][3];
#pragma unroll
        for (int dy = 0; dy < 3; dy++) {
            int i = yy - 1 + dy;
#pragma unroll
            for (int dxx = 0; dxx < 3; dxx++) {
                int jx = xx - 1 + dxx;
                v[dy][dxx] = (i >= 0 && i < 128 && jx >= 0 && jx < 128)
                             ? fmaxf(__ldg(src + i * 128 + jx), 0.f) : 0.f;
            }
        }
        const float* wsr = ws + ci * 16;
#pragma unroll
        for (int di = 0; di < 2; di++)
#pragma unroll
            for (int dj = 0; dj < 2; dj++)
                a00 += v[di][dj] * wsr[(3 - 2*di) * 4 + (3 - 2*dj)];
#pragma unroll
        for (int di = 0; di < 2; di++)
#pragma unroll
            for (int dj = 0; dj < 2; dj++)
                a01 += v[di][dj+1] * wsr[(3 - 2*di) * 4 + (2 - 2*dj)];
#pragma unroll
        for (int di = 0; di < 2; di++)
#pragma unroll
            for (int dj = 0; dj < 2; dj++)
                a10 += v[di+1][dj] * wsr[(2 - 2*di) * 4 + (3 - 2*dj)];
#pragma unroll
        for (int di = 0; di < 2; di++)
#pragma unroll
            for (int dj = 0; dj < 2; dj++)
                a11 += v[di+1][dj+1] * wsr[(2 - 2*di) * 4 + (2 - 2*dj)];
    }

    float bias = __ldg(&b0[0]);
    int base = b * PIX + (2 * yy) * 256 + 2 * xx;
    out[base]       = 1.0f / (1.0f + expf(-(a00 + bias)));
    out[base + 1]   = 1.0f / (1.0f + expf(-(a01 + bias)));
    out[base + 256] = 1.0f / (1.0f + expf(-(a10 + bias)));
    out[base + 257] = 1.0f / (1.0f + expf(-(a11 + bias)));
}

// ---------------- driver ----------------
extern "C" void kernel_launch(void* const* d_in, const int* in_sizes, int n_in,
                              void* d_out, int out_size)
{
    const float* sig   = (const float*)d_in[0];
    const float* trans = (const float*)d_in[1];
    const float* w_d0  = (const float*)d_in[2];
    const float* w_d1  = (const float*)d_in[3];
    const float* g_d1  = (const float*)d_in[4];
    const float* b_d1  = (const float*)d_in[5];
    const float* w_d2  = (const float*)d_in[6];
    const float* g_d2  = (const float*)d_in[7];
    const float* b_d2  = (const float*)d_in[8];
    const float* w_d3  = (const float*)d_in[9];
    const float* g_d3  = (const float*)d_in[10];
    const float* b_d3  = (const float*)d_in[11];
    const float* w_d4  = (const float*)d_in[12];
    const float* w_u4  = (const float*)d_in[13];
    const float* g_u4p = (const float*)d_in[14];
    const float* b_u4p = (const float*)d_in[15];
    const float* w_u3  = (const float*)d_in[16];
    const float* g_u3p = (const float*)d_in[17];
    const float* b_u3p = (const float*)d_in[18];
    const float* w_u2  = (const float*)d_in[19];
    const float* g_u2p = (const float*)d_in[20];
    const float* b_u2p = (const float*)d_in[21];
    const float* w_u1  = (const float*)d_in[22];
    const float* g_u1p = (const float*)d_in[23];
    const float* b_u1p = (const float*)d_in[24];
    const float* w_u0  = (const float*)d_in[25];
    const float* b_u0  = (const float*)d_in[26];

    float* outp = (float*)d_out;
    float* out_rec = outp + IMG;
    int copy_rec = (out_size >= 2 * IMG) ? 1 : 0;

    k_backproject<<<PIX / 256, 256>>>(sig, trans);
    k_minmax_init<<<1, 1>>>();
    k_minmax_reduce<<<256, 256>>>();
    k_normalize<<<(IMG + 255) / 256, 256>>>(out_rec, copy_rec);

    k_conv_d0<<<1024, 256>>>(w_d0);
    k_conv_d1<<<dim3(1024, 2), 256>>>(w_d1);
    k_bns_h1<<<128, 256>>>(g_d1, b_d1);
    k_bna_h1<<<BB*128*4096/256, 256>>>();
    k_conv_d2<<<dim3(256, 4), 256>>>(w_d2);
    k_bns_h2<<<256, 256>>>(g_d2, b_d2);
    k_bna_h2<<<BB*256*1024/256, 256>>>();
    k_conv_d3<<<dim3(64, 8), 256>>>(w_d3);
    k_bns_h3<<<512, 256>>>(g_d3, b_d3);
    k_bna_h3<<<BB*512*256/256, 256>>>();
    k_conv_d4<<<dim3(16, 8), 256>>>(w_d4);

    k_repack<<<(512*512*16 + 255)/256, 256>>>(w_u4, 512, 512);
    k_deconv_u4<<<dim3(16, 8, 4), 256>>>();
    k_bns_u4<<<512, 256>>>(g_u4p, b_u4p);
    k_bna_u4<<<BB*512*256/256, 256>>>();

    k_repack<<<(1024*256*16 + 255)/256, 256>>>(w_u3, 1024, 256);
    k_deconv_u3<<<dim3(64, 4, 4), 256>>>();
    k_bns_u3<<<256, 256>>>(g_u3p, b_u3p);
    k_bna_u3<<<BB*256*1024/256, 256>>>();

    k_repack<<<(512*128*16 + 255)/256, 256>>>(w_u2, 512, 128);
    k_deconv_u2<<<dim3(256, 2, 4), 256>>>();
    k_bns_u2<<<128, 256>>>(g_u2p, b_u2p);
    k_bna_u2<<<BB*128*4096/256, 256>>>();

    k_repack<<<(256*64*16 + 255)/256, 256>>>(w_u1, 256, 64);
    k_deconv_u1<<<dim3(1024, 1, 4), 256>>>();
    k_bns_u1<<<64, 256>>>(g_u1p, b_u1p);
    k_bna_u1<<<BB*64*16384/256, 256>>>();

    k_deconv_u0<<<(BB*128*128 + 255) / 256, 256>>>(w_u0, b_u0, outp);
}